// round 16
// baseline (speedup 1.0000x reference)
#include <cuda_runtime.h>

// 2-layer LSTM (H=30, IN=1) + linear head, B=512, T=2048.
// EXACT Round-12 champion structure (815us): block = 1 element, 128 thr =
// 4 warps, QUAD layout (g = tid&3: 0=i,1=f,2=g,3=o; u = tid>>2; units 30,31
// pad). Weight rows register-resident f32x2, sigmoid lanes pre-scaled by 0.5
// (tanh form), activations = hardware tanh.approx.f32. Iter n: L1 step n +
// L2 step n-1 fused, ONE __syncthreads/iter, ping-pong buffers, scalar sx[n]
// loads, biases added in the TAIL, emit = pre2 + bfc (all as in the 815us
// kernel). SINGLE change this round: steady unroll x4 -> x2 so the loop
// body (~3KB) fits the ~6KB L0 I-cache with margin (x4 was ~6.1KB,
// borderline; x8 at ~12KB regressed).

#define Hs 30
#define Ts 2048
#define Bs 512

typedef unsigned long long ull;

__device__ __forceinline__ ull pk(float lo, float hi) {
    ull r; asm("mov.b64 %0, {%1, %2};" : "=l"(r) : "f"(lo), "f"(hi)); return r;
}
__device__ __forceinline__ void fma2(ull& d, ull a, ull b) {
    asm("fma.rn.f32x2 %0, %1, %2, %3;" : "=l"(d) : "l"(a), "l"(b), "l"(d));
}
__device__ __forceinline__ ull add2(ull a, ull b) {
    ull r; asm("add.rn.f32x2 %0, %1, %2;" : "=l"(r) : "l"(a), "l"(b)); return r;
}
__device__ __forceinline__ float hadd(ull a) {
    float lo, hi; asm("mov.b64 {%0, %1}, %2;" : "=f"(lo), "=f"(hi) : "l"(a)); return lo + hi;
}
__device__ __forceinline__ float tanha(float x) {
    float y; asm("tanh.approx.f32 %0, %1;" : "=f"(y) : "f"(x)); return y;
}
__device__ __forceinline__ float act(float p, float aa, float cc) {
    return fmaf(aa, tanha(p), cc);   // sigmoid lanes: 0.5*t+0.5; g lane: t
}

// One fused iteration. Reads H1R=h1[n-1], H2R=h2[n-2]; writes H1W=h1[n],
// H2W=h2[n-1]. Lane 127 (w2i=0, w2h=w_fc, b2=0): pre2 == out[n-2]-bfc.
#define ITER(H1R, H2R, H1W, H2W, XV, OUTP, DO_EMIT) { \
    const ulonglong2* hp1 = (const ulonglong2*)(H1R); \
    const ulonglong2* hp2 = (const ulonglong2*)(H2R); \
    float xb = fmaf((XV), k0, b1); \
    ull a0 = 0ull, a1 = 0ull, e0 = 0ull, e1 = 0ull, d0 = 0ull, d1 = 0ull; \
    _Pragma("unroll") \
    for (int k = 0; k < 7; k++) { \
        ulonglong2 v1 = hp1[k]; \
        ulonglong2 v2 = hp2[k]; \
        fma2(a0, w1p[2 * k],     v1.x); \
        fma2(a1, w1p[2 * k + 1], v1.y); \
        fma2(e0, w2i[2 * k],     v1.x); \
        fma2(e1, w2i[2 * k + 1], v1.y); \
        fma2(d0, w2h[2 * k],     v2.x); \
        fma2(d1, w2h[2 * k + 1], v2.y); \
    } \
    { ull v1t = ((const ull*)(H1R))[14], v2t = ((const ull*)(H2R))[14]; \
      fma2(a0, w1p[14], v1t); \
      fma2(e0, w2i[14], v1t); \
      fma2(d0, w2h[14], v2t); } \
    float pre1 = xb + hadd(add2(a0, a1)); \
    float pre2 = b2 + hadd(add2(add2(e0, e1), add2(d0, d1))); \
    if (DO_EMIT) { if (tid == 127) *(OUTP) = pre2 + bfc; } \
    float av = act(pre1, aa, cc); \
    float zv = act(pre2, aa, cc); \
    { \
        float gi = __shfl_sync(0xffffffffu, av, base); \
        float gf = __shfl_sync(0xffffffffu, av, base + 1); \
        float gg = __shfl_sync(0xffffffffu, av, base + 2); \
        c1 = fmaf(gf, c1, gi * gg); \
        if (g == 3) (H1W)[u] = av * tanha(c1); \
    } \
    { \
        float qi = __shfl_sync(0xffffffffu, zv, base); \
        float qf = __shfl_sync(0xffffffffu, zv, base + 1); \
        float qg = __shfl_sync(0xffffffffu, zv, base + 2); \
        c2 = fmaf(qf, c2, qi * qg); \
        if (g == 3) (H2W)[u] = zv * tanha(c2); \
    } \
    __syncthreads(); \
}

__global__ void __launch_bounds__(128, 4) lstm_kernel(
    const float* __restrict__ x,
    const float* __restrict__ w_ih1, const float* __restrict__ w_hh1,
    const float* __restrict__ b_ih1, const float* __restrict__ b_hh1,
    const float* __restrict__ w_ih2, const float* __restrict__ w_hh2,
    const float* __restrict__ b_ih2, const float* __restrict__ b_hh2,
    const float* __restrict__ w_fc,  const float* __restrict__ b_fc,
    float* __restrict__ out)
{
    __shared__ __align__(16) float sx[Ts];
    __shared__ __align__(16) float h1A[32], h1B[32];
    __shared__ __align__(16) float h2A[32], h2B[32];

    const int tid  = threadIdx.x;
    const int g    = tid & 3;
    const int u    = tid >> 2;
    const int lane = tid & 31;
    const int base = lane & ~3;
    const int b    = blockIdx.x;

    {   // coalesced x preload
        const float4* xb4 = (const float4*)(x + (size_t)b * Ts);
        float4* sx4 = (float4*)sx;
        #pragma unroll
        for (int i = 0; i < Ts / 4 / 128; i++) sx4[tid + i * 128] = xb4[tid + i * 128];
    }
    if (tid < 32) {
        h1A[tid] = 0.0f; h1B[tid] = 0.0f;
        h2A[tid] = 0.0f; h2B[tid] = 0.0f;
    }

    // Per-lane input scale: sigmoid lanes 0.5 (tanh(x/2) form), g lane 1.0.
    const float s = (g == 2) ? 1.0f : 0.5f;
    const bool  fc_lane = (tid == 127);

    // Register-resident weight rows, PRE-SCALED by s. FC lane (127):
    // w2i = 0, w2h = w_fc (unscaled), b2 = 0 -> its pre2 = w_fc . h2[n-2].
    const int row = g * Hs + ((u < Hs) ? u : Hs - 1);
    ull w1p[15], w2i[15], w2h[15];
    {
        const float* r1  = w_hh1 + row * Hs;
        const float* r2i = w_ih2 + row * Hs;
        const float* r2h = fc_lane ? w_fc : (w_hh2 + row * Hs);
        const float  s2i = fc_lane ? 0.0f : s;
        const float  s2h = fc_lane ? 1.0f : s;
        #pragma unroll
        for (int k = 0; k < 15; k++) {
            w1p[k] = pk(s * r1[2 * k],    s * r1[2 * k + 1]);
            w2i[k] = pk(s2i * r2i[2 * k], s2i * r2i[2 * k + 1]);
            w2h[k] = pk(s2h * r2h[2 * k], s2h * r2h[2 * k + 1]);
        }
    }
    const float k0  = s * w_ih1[row];
    const float b1  = s * (b_ih1[row] + b_hh1[row]);
    const float bfc = b_fc[0];
    const float b2  = fc_lane ? 0.0f : s * (b_ih2[row] + b_hh2[row]);

    const float aa = (g == 2) ? 1.0f : 0.5f;
    const float cc = (g == 2) ? 0.0f : 0.5f;

    float c1 = 0.0f, c2 = 0.0f;
    float* __restrict__ outb = out + (size_t)b * Ts;

    __syncthreads();

    // ---- Prologue n = 0: L1 step 0 only (h1[-1]=0) -> h1B ----
    {
        float av = act(fmaf(sx[0], k0, b1), aa, cc);
        float gi = __shfl_sync(0xffffffffu, av, base);
        float gg = __shfl_sync(0xffffffffu, av, base + 2);
        c1 = gi * gg;
        if (g == 3) h1B[u] = av * tanha(c1);
        __syncthreads();
    }

    // ---- n = 1: read B (h2[-1]=0), write A; no emit ----
    ITER(h1B, h2B, h1A, h2A, sx[1], outb, false);

    // ---- Steady: n = 2..2047, unrolled x2 (one ping-pong pair) ----
    const float* sxp = sx + 2;
    float* op = outb;   // op[0] = out[n-2] at the even step
    #pragma unroll 1
    for (int k2 = 0; k2 < 1023; k2++) {
        ITER(h1A, h2A, h1B, h2B, sxp[0], op,     true);
        ITER(h1B, h2B, h1A, h2A, sxp[1], op + 1, true);
        sxp += 2;
        op  += 2;
    }
    // After steady: h1A = h1[2047], h2A = h2[2046]; emitted out[0..2045].

    // ---- Epilogue: L2-only step 2047; lane 127 emits out[2046] ----
    {
        const ulonglong2* hp1 = (const ulonglong2*)h1A;
        const ulonglong2* hp2 = (const ulonglong2*)h2A;
        ull e0 = 0ull, e1 = 0ull, d0 = 0ull, d1 = 0ull;
        #pragma unroll
        for (int k = 0; k < 7; k++) {
            ulonglong2 v1 = hp1[k];
            ulonglong2 v2 = hp2[k];
            fma2(e0, w2i[2 * k],     v1.x);
            fma2(e1, w2i[2 * k + 1], v1.y);
            fma2(d0, w2h[2 * k],     v2.x);
            fma2(d1, w2h[2 * k + 1], v2.y);
        }
        fma2(e0, w2i[14], ((const ull*)h1A)[14]);
        fma2(d0, w2h[14], ((const ull*)h2A)[14]);
        float pre2 = b2 + hadd(add2(add2(e0, e1), add2(d0, d1)));
        if (tid == 127) outb[Ts - 2] = pre2 + bfc;
        float zv = act(pre2, aa, cc);
        float qi = __shfl_sync(0xffffffffu, zv, base);
        float qf = __shfl_sync(0xffffffffu, zv, base + 1);
        float qg = __shfl_sync(0xffffffffu, zv, base + 2);
        c2 = fmaf(qf, c2, qi * qg);
        if (g == 3) h2B[u] = zv * tanha(c2);
        __syncthreads();
    }
    // ---- Final: out[2047] = w_fc . h2[2047] + bfc (lane 127 mini-dot) ----
    if (tid == 127) {
        const ulonglong2* hp2 = (const ulonglong2*)h2B;
        ull d0 = 0ull, d1 = 0ull;
        #pragma unroll
        for (int k = 0; k < 7; k++) {
            ulonglong2 v2 = hp2[k];
            fma2(d0, w2h[2 * k],     v2.x);
            fma2(d1, w2h[2 * k + 1], v2.y);
        }
        fma2(d0, w2h[14], ((const ull*)h2B)[14]);
        outb[Ts - 1] = hadd(add2(d0, d1)) + bfc;
    }
}

extern "C" void kernel_launch(void* const* d_in, const int* in_sizes, int n_in,
                              void* d_out, int out_size) {
    (void)in_sizes; (void)n_in; (void)out_size;
    lstm_kernel<<<Bs, 128>>>(
        (const float*)d_in[0],
        (const float*)d_in[1], (const float*)d_in[2],
        (const float*)d_in[3], (const float*)d_in[4],
        (const float*)d_in[5], (const float*)d_in[6],
        (const float*)d_in[7], (const float*)d_in[8],
        (const float*)d_in[9], (const float*)d_in[10],
        (float*)d_out);
}

// round 17
// speedup vs baseline: 1.0464x; 1.0464x over previous
#include <cuda_runtime.h>

// 2-layer LSTM (H=30, IN=1) + linear head, B=512, T=2048.
// CHAMPION RE-BENCH (byte-identical to the 815.5us Round-12 kernel).
// Block = 1 element, 128 thr = 4 warps, QUAD layout
// (g = tid&3: 0=i,1=f,2=g,3=o; u = tid>>2; units 30,31 pad). Weight rows
// register-resident f32x2. Iter n: L1 step n + L2 step n-1 fused, ONE
// __syncthreads/iter, ping-pong buffers, x4-unrolled steady loop. FC head
// folded into lane 127 (w2i=0, b2=0, w2h=w_fc -> pre2 == out[n-2]-bfc).
// All activations via hardware tanh.approx.f32:
//   sigmoid(x) = 0.5*tanh(x/2)+0.5  -> weights pre-scaled by 0.5
//   g-gate / cell tanh = tanh.approx directly.

#define Hs 30
#define Ts 2048
#define Bs 512

typedef unsigned long long ull;

__device__ __forceinline__ ull pk(float lo, float hi) {
    ull r; asm("mov.b64 %0, {%1, %2};" : "=l"(r) : "f"(lo), "f"(hi)); return r;
}
__device__ __forceinline__ void fma2(ull& d, ull a, ull b) {
    asm("fma.rn.f32x2 %0, %1, %2, %3;" : "=l"(d) : "l"(a), "l"(b), "l"(d));
}
__device__ __forceinline__ ull add2(ull a, ull b) {
    ull r; asm("add.rn.f32x2 %0, %1, %2;" : "=l"(r) : "l"(a), "l"(b)); return r;
}
__device__ __forceinline__ float hadd(ull a) {
    float lo, hi; asm("mov.b64 {%0, %1}, %2;" : "=f"(lo), "=f"(hi) : "l"(a)); return lo + hi;
}
__device__ __forceinline__ float tanha(float x) {
    float y; asm("tanh.approx.f32 %0, %1;" : "=f"(y) : "f"(x)); return y;
}
__device__ __forceinline__ float act(float p, float aa, float cc) {
    return fmaf(aa, tanha(p), cc);   // sigmoid lanes: 0.5*t+0.5; g lane: t
}

// One fused iteration. Reads H1R=h1[n-1], H2R=h2[n-2]; writes H1W=h1[n],
// H2W=h2[n-1]. Lane 127 (w2i=0,b2=0,w2h=w_fc): pre2 == out[n-2]-bfc.
#define ITER(H1R, H2R, H1W, H2W, XV, OUTP, DO_EMIT) { \
    const ulonglong2* hp1 = (const ulonglong2*)(H1R); \
    const ulonglong2* hp2 = (const ulonglong2*)(H2R); \
    float xb = fmaf((XV), k0, b1); \
    ull a0 = 0ull, a1 = 0ull, e0 = 0ull, e1 = 0ull, d0 = 0ull, d1 = 0ull; \
    _Pragma("unroll") \
    for (int k = 0; k < 7; k++) { \
        ulonglong2 v1 = hp1[k]; \
        ulonglong2 v2 = hp2[k]; \
        fma2(a0, w1p[2 * k],     v1.x); \
        fma2(a1, w1p[2 * k + 1], v1.y); \
        fma2(e0, w2i[2 * k],     v1.x); \
        fma2(e1, w2i[2 * k + 1], v1.y); \
        fma2(d0, w2h[2 * k],     v2.x); \
        fma2(d1, w2h[2 * k + 1], v2.y); \
    } \
    { ull v1t = ((const ull*)(H1R))[14], v2t = ((const ull*)(H2R))[14]; \
      fma2(a0, w1p[14], v1t); \
      fma2(e0, w2i[14], v1t); \
      fma2(d0, w2h[14], v2t); } \
    float pre1 = xb + hadd(add2(a0, a1)); \
    float pre2 = b2 + hadd(add2(add2(e0, e1), add2(d0, d1))); \
    if (DO_EMIT) { if (tid == 127) *(OUTP) = pre2 + bfc; } \
    float av = act(pre1, aa, cc); \
    float zv = act(pre2, aa, cc); \
    { \
        float gi = __shfl_sync(0xffffffffu, av, base); \
        float gf = __shfl_sync(0xffffffffu, av, base + 1); \
        float gg = __shfl_sync(0xffffffffu, av, base + 2); \
        c1 = fmaf(gf, c1, gi * gg); \
        if (g == 3) (H1W)[u] = av * tanha(c1); \
    } \
    { \
        float qi = __shfl_sync(0xffffffffu, zv, base); \
        float qf = __shfl_sync(0xffffffffu, zv, base + 1); \
        float qg = __shfl_sync(0xffffffffu, zv, base + 2); \
        c2 = fmaf(qf, c2, qi * qg); \
        if (g == 3) (H2W)[u] = zv * tanha(c2); \
    } \
    __syncthreads(); \
}

__global__ void __launch_bounds__(128, 4) lstm_kernel(
    const float* __restrict__ x,
    const float* __restrict__ w_ih1, const float* __restrict__ w_hh1,
    const float* __restrict__ b_ih1, const float* __restrict__ b_hh1,
    const float* __restrict__ w_ih2, const float* __restrict__ w_hh2,
    const float* __restrict__ b_ih2, const float* __restrict__ b_hh2,
    const float* __restrict__ w_fc,  const float* __restrict__ b_fc,
    float* __restrict__ out)
{
    __shared__ __align__(16) float sx[Ts];
    __shared__ __align__(16) float h1A[32], h1B[32];
    __shared__ __align__(16) float h2A[32], h2B[32];

    const int tid  = threadIdx.x;
    const int g    = tid & 3;
    const int u    = tid >> 2;
    const int lane = tid & 31;
    const int base = lane & ~3;
    const int b    = blockIdx.x;

    {   // coalesced x preload
        const float4* xb4 = (const float4*)(x + (size_t)b * Ts);
        float4* sx4 = (float4*)sx;
        #pragma unroll
        for (int i = 0; i < Ts / 4 / 128; i++) sx4[tid + i * 128] = xb4[tid + i * 128];
    }
    if (tid < 32) {
        h1A[tid] = 0.0f; h1B[tid] = 0.0f;
        h2A[tid] = 0.0f; h2B[tid] = 0.0f;
    }

    // Per-lane input scale: sigmoid lanes 0.5 (tanh(x/2) form), g lane 1.0.
    const float s = (g == 2) ? 1.0f : 0.5f;
    const bool  fc_lane = (tid == 127);

    // Register-resident weight rows, PRE-SCALED by s. FC lane (127):
    // w2i = 0, w2h = w_fc (unscaled), b2 = 0 -> its pre2 = w_fc . h2[n-2].
    const int row = g * Hs + ((u < Hs) ? u : Hs - 1);
    ull w1p[15], w2i[15], w2h[15];
    {
        const float* r1  = w_hh1 + row * Hs;
        const float* r2i = w_ih2 + row * Hs;
        const float* r2h = fc_lane ? w_fc : (w_hh2 + row * Hs);
        const float  s2i = fc_lane ? 0.0f : s;
        const float  s2h = fc_lane ? 1.0f : s;
        #pragma unroll
        for (int k = 0; k < 15; k++) {
            w1p[k] = pk(s * r1[2 * k],    s * r1[2 * k + 1]);
            w2i[k] = pk(s2i * r2i[2 * k], s2i * r2i[2 * k + 1]);
            w2h[k] = pk(s2h * r2h[2 * k], s2h * r2h[2 * k + 1]);
        }
    }
    const float k0  = s * w_ih1[row];
    const float b1  = s * (b_ih1[row] + b_hh1[row]);
    const float bfc = b_fc[0];
    const float b2  = fc_lane ? 0.0f : s * (b_ih2[row] + b_hh2[row]);

    // Activation output constants: sigmoid lanes 0.5*t+0.5; g lane t.
    const float aa = (g == 2) ? 1.0f : 0.5f;
    const float cc = (g == 2) ? 0.0f : 0.5f;

    float c1 = 0.0f, c2 = 0.0f;
    float* __restrict__ outb = out + (size_t)b * Ts;

    __syncthreads();

    // ---- Prologue n = 0: L1 step 0 only (h1[-1]=0) -> h1B ----
    {
        float av = act(fmaf(sx[0], k0, b1), aa, cc);
        float gi = __shfl_sync(0xffffffffu, av, base);
        float gg = __shfl_sync(0xffffffffu, av, base + 2);
        c1 = gi * gg;
        if (g == 3) h1B[u] = av * tanha(c1);
        __syncthreads();
    }

    // ---- n = 1: read B (h2[-1]=0), write A; no emit ----
    ITER(h1B, h2B, h1A, h2A, sx[1], outb, false);

    // ---- Steady: n = 2..2047, unrolled x4 (two ping-pong pairs) ----
    const float* sxp = sx + 2;
    float* op = outb;   // op[0] = out[n-2] at the first (even) step
    #pragma unroll 1
    for (int k4 = 0; k4 < 511; k4++) {
        ITER(h1A, h2A, h1B, h2B, sxp[0], op,     true);
        ITER(h1B, h2B, h1A, h2A, sxp[1], op + 1, true);
        ITER(h1A, h2A, h1B, h2B, sxp[2], op + 2, true);
        ITER(h1B, h2B, h1A, h2A, sxp[3], op + 3, true);
        sxp += 4;
        op  += 4;
    }
    ITER(h1A, h2A, h1B, h2B, sxp[0], op,     true);
    ITER(h1B, h2B, h1A, h2A, sxp[1], op + 1, true);
    // After steady: h1A = h1[2047], h2A = h2[2046]; emitted out[0..2045].

    // ---- Epilogue: L2-only step 2047; lane 127 emits out[2046] ----
    {
        const ulonglong2* hp1 = (const ulonglong2*)h1A;
        const ulonglong2* hp2 = (const ulonglong2*)h2A;
        ull e0 = 0ull, e1 = 0ull, d0 = 0ull, d1 = 0ull;
        #pragma unroll
        for (int k = 0; k < 7; k++) {
            ulonglong2 v1 = hp1[k];
            ulonglong2 v2 = hp2[k];
            fma2(e0, w2i[2 * k],     v1.x);
            fma2(e1, w2i[2 * k + 1], v1.y);
            fma2(d0, w2h[2 * k],     v2.x);
            fma2(d1, w2h[2 * k + 1], v2.y);
        }
        fma2(e0, w2i[14], ((const ull*)h1A)[14]);
        fma2(d0, w2h[14], ((const ull*)h2A)[14]);
        float pre2 = b2 + hadd(add2(add2(e0, e1), add2(d0, d1)));
        if (tid == 127) outb[Ts - 2] = pre2 + bfc;
        float zv = act(pre2, aa, cc);
        float qi = __shfl_sync(0xffffffffu, zv, base);
        float qf = __shfl_sync(0xffffffffu, zv, base + 1);
        float qg = __shfl_sync(0xffffffffu, zv, base + 2);
        c2 = fmaf(qf, c2, qi * qg);
        if (g == 3) h2B[u] = zv * tanha(c2);
        __syncthreads();
    }
    // ---- Final: out[2047] = w_fc . h2[2047] + bfc (lane 127 mini-dot) ----
    if (tid == 127) {
        const ulonglong2* hp2 = (const ulonglong2*)h2B;
        ull d0 = 0ull, d1 = 0ull;
        #pragma unroll
        for (int k = 0; k < 7; k++) {
            ulonglong2 v2 = hp2[k];
            fma2(d0, w2h[2 * k],     v2.x);
            fma2(d1, w2h[2 * k + 1], v2.y);
        }
        fma2(d0, w2h[14], ((const ull*)h2B)[14]);
        outb[Ts - 1] = hadd(add2(d0, d1)) + bfc;
    }
}

extern "C" void kernel_launch(void* const* d_in, const int* in_sizes, int n_in,
                              void* d_out, int out_size) {
    (void)in_sizes; (void)n_in; (void)out_size;
    lstm_kernel<<<Bs, 128>>>(
        (const float*)d_in[0],
        (const float*)d_in[1], (const float*)d_in[2],
        (const float*)d_in[3], (const float*)d_in[4],
        (const float*)d_in[5], (const float*)d_in[6],
        (const float*)d_in[7], (const float*)d_in[8],
        (const float*)d_in[9], (const float*)d_in[10],
        (float*)d_out);
}